// round 15
// baseline (speedup 1.0000x reference)
#include <cuda_runtime.h>
#include <cuda_bf16.h>
#include <cuda_fp16.h>
#include <math.h>
#include <stdint.h>

// ---------------------------------------------------------------------------
// CodeShellAttention round 15: BK 32 -> 64 in both GEMMs (2-stage double
// buffer, one barrier + one cp-wait per 64-K chunk — halves per-chunk serial
// overhead). Precision scheme and flash unchanged from R14.
// ---------------------------------------------------------------------------

#define S_LEN  2048
#define HID    4096
#define NH     32
#define NKV    8
#define HD     128
#define QKV_N  6144
#define KV_DIM 1024
#define HALF   64

__device__ float g_cos[S_LEN * HALF];
__device__ float g_sin[S_LEN * HALF];

__device__ __nv_bfloat16 g_Xhi[S_LEN * HID];
__device__ __nv_bfloat16 g_Xlo[S_LEN * HID];
__device__ __nv_bfloat16 g_Wq_hi[HID * QKV_N];
__device__ __nv_bfloat16 g_Wq_lo[HID * QKV_N];
__device__ __half        g_Wpf[HID * HID];

__device__ __nv_bfloat16 g_Qhi[S_LEN * HID];
__device__ __nv_bfloat16 g_Qlo[S_LEN * HID];
__device__ __nv_bfloat16 g_Khi[S_LEN * KV_DIM];
__device__ __nv_bfloat16 g_Klo[S_LEN * KV_DIM];
__device__ __half        g_Vf[S_LEN * KV_DIM];
__device__ __half        g_Ahf[S_LEN * HID];
__device__ __half        g_Alf[S_LEN * HID];

// ========================= helpers =========================================
__device__ __forceinline__ uint32_t smem_u32(const void* p) {
    uint32_t a;
    asm("{ .reg .u64 t; cvta.to.shared.u64 t, %1; cvt.u32.u64 %0, t; }"
        : "=r"(a) : "l"(p));
    return a;
}

__device__ __forceinline__ void ldsm4(uint32_t* r, uint32_t addr) {
    asm volatile("ldmatrix.sync.aligned.m8n8.x4.shared.b16 {%0,%1,%2,%3}, [%4];"
                 : "=r"(r[0]), "=r"(r[1]), "=r"(r[2]), "=r"(r[3]) : "r"(addr));
}

__device__ __forceinline__ void ldsm4t(uint32_t* r, uint32_t addr) {
    asm volatile("ldmatrix.sync.aligned.m8n8.x4.trans.shared.b16 {%0,%1,%2,%3}, [%4];"
                 : "=r"(r[0]), "=r"(r[1]), "=r"(r[2]), "=r"(r[3]) : "r"(addr));
}

__device__ __forceinline__ void mma16816(float* d, const uint32_t* a,
                                         const uint32_t* b) {
    asm volatile(
        "mma.sync.aligned.m16n8k16.row.col.f32.bf16.bf16.f32 "
        "{%0,%1,%2,%3}, {%4,%5,%6,%7}, {%8,%9}, {%0,%1,%2,%3};"
        : "+f"(d[0]), "+f"(d[1]), "+f"(d[2]), "+f"(d[3])
        : "r"(a[0]), "r"(a[1]), "r"(a[2]), "r"(a[3]), "r"(b[0]), "r"(b[1]));
}

__device__ __forceinline__ void mma16816h(float* d, const uint32_t* a,
                                          const uint32_t* b) {
    asm volatile(
        "mma.sync.aligned.m16n8k16.row.col.f32.f16.f16.f32 "
        "{%0,%1,%2,%3}, {%4,%5,%6,%7}, {%8,%9}, {%0,%1,%2,%3};"
        : "+f"(d[0]), "+f"(d[1]), "+f"(d[2]), "+f"(d[3])
        : "r"(a[0]), "r"(a[1]), "r"(a[2]), "r"(a[3]), "r"(b[0]), "r"(b[1]));
}

__device__ __forceinline__ void split2(float x, float y, uint32_t& hi, uint32_t& lo)
{
    uint32_t bx = __float_as_uint(x), by = __float_as_uint(y);
    hi = __byte_perm(bx, by, 0x7632);
    float hx = __uint_as_float(bx & 0xFFFF0000u);
    float hy = __uint_as_float(by & 0xFFFF0000u);
    __nv_bfloat162 l = __floats2bfloat162_rn(x - hx, y - hy);
    lo = *reinterpret_cast<uint32_t*>(&l);
}

__device__ __forceinline__ void split2h(float x, float y, uint32_t& hi, uint32_t& lo)
{
    __half2 h = __floats2half2_rn(x, y);
    float hx = __half2float(__low2half(h));
    float hy = __half2float(__high2half(h));
    __half2 l = __floats2half2_rn(x - hx, y - hy);
    hi = *reinterpret_cast<uint32_t*>(&h);
    lo = *reinterpret_cast<uint32_t*>(&l);
}

__device__ __forceinline__ uint32_t pack2h(float x, float y)
{
    __half2 h = __floats2half2_rn(x, y);
    return *reinterpret_cast<uint32_t*>(&h);
}

__device__ __forceinline__ void cp16(uint32_t saddr, const void* gaddr) {
    asm volatile("cp.async.cg.shared.global [%0], [%1], 16;"
                 :: "r"(saddr), "l"(gaddr) : "memory");
}
#define CP_COMMIT() asm volatile("cp.async.commit_group;" ::: "memory")
#define CP_WAIT0()  asm volatile("cp.async.wait_group 0;" ::: "memory")
#define CP_WAIT1()  asm volatile("cp.async.wait_group 1;" ::: "memory")

// ========================= RoPE tables =====================================
__global__ void rope_table_kernel(const int* __restrict__ positions)
{
    int i = blockIdx.x * blockDim.x + threadIdx.x;
    if (i >= S_LEN * HALF) return;
    int m = i >> 6;
    int d = i & 63;
    double p    = (double)positions[m];
    double invf = pow(10000.0, -((double)d) / 64.0);
    double a    = p * invf;
    g_cos[i] = (float)cos(a);
    g_sin[i] = (float)sin(a);
}

// ========================= split passes ====================================
__global__ void split_kernel(const float4* __restrict__ in,
                             uint2* __restrict__ hi, uint2* __restrict__ lo,
                             int n4)
{
    int i = blockIdx.x * blockDim.x + threadIdx.x;
    if (i >= n4) return;
    float4 v = in[i];
    uint32_t h01, l01, h23, l23;
    split2(v.x, v.y, h01, l01);
    split2(v.z, v.w, h23, l23);
    hi[i] = make_uint2(h01, h23);
    lo[i] = make_uint2(l01, l23);
}

__global__ void split_half_kernel(const float4* __restrict__ in,
                                  uint2* __restrict__ out, int n4)
{
    int i = blockIdx.x * blockDim.x + threadIdx.x;
    if (i >= n4) return;
    float4 v = in[i];
    out[i] = make_uint2(pack2h(v.x, v.y), pack2h(v.z, v.w));
}

// ========================= QKV GEMM (bf16 3-term, BK=64) ===================
// BM=128 BN=256 BK=64, 512 threads, 2 stages of 96KB.
// Stage: Ahi[0,16K) Alo[16K,32K) Bhi[32K,64K) Blo[64K,96K).
// A rows: 128B (8 granules, swizzle g^(row&7)); B rows: 512B (g^(k&7)).
#define G2_STG   98304
#define G2_SMEM  (2 * G2_STG)
#define G2_ESTR  260

__global__ __launch_bounds__(512, 1)
void hmma_gemm2(const __nv_bfloat16* __restrict__ Ahi,
                const __nv_bfloat16* __restrict__ Alo,
                const __nv_bfloat16* __restrict__ Bhi,
                const __nv_bfloat16* __restrict__ Blo,
                const float* __restrict__ bias,
                int N, int K)
{
    extern __shared__ char smem[];
    const uint32_t sb = smem_u32(smem);
    const int tid  = threadIdx.x;
    const int lane = tid & 31;
    const int warp = tid >> 5;
    const int wm   = warp >> 2;
    const int wn   = warp & 3;
    const int bm   = blockIdx.y * 128;
    const int bn   = blockIdx.x * 256;
    const int nchunk = K >> 6;

    // A: 1024 granule positions (row 0..127, g 0..7) -> 2/thread
    const int ap0 = tid * 2, ap1 = tid * 2 + 1;
    const int ar0 = ap0 >> 3, ag0 = ap0 & 7;
    const int ar1 = ap1 >> 3, ag1 = ap1 & 7;
    const uint32_t a_d0 = (uint32_t)(ar0 * 128 + ((ag0 ^ (ar0 & 7)) << 4));
    const uint32_t a_d1 = (uint32_t)(ar1 * 128 + ((ag1 ^ (ar1 & 7)) << 4));
    const size_t a_s0 = (size_t)(bm + ar0) * K + ag0 * 8;
    const size_t a_s1 = (size_t)(bm + ar1) * K + ag1 * 8;

    // B: 2048 positions (k 0..63, g 0..31) -> 4/thread
    int bk[4], bg[4];
    uint32_t b_d[4];
#pragma unroll
    for (int i = 0; i < 4; i++) {
        const int q = tid * 4 + i;
        bk[i] = q >> 5; bg[i] = q & 31;
        b_d[i] = (uint32_t)(bk[i] * 512 + ((bg[i] ^ (bk[i] & 7)) << 4));
    }

    auto issue = [&](int s, int c) {
        const uint32_t st = sb + s * G2_STG;
        const int k0 = c << 6;
        cp16(st + a_d0,         Ahi + a_s0 + k0);
        cp16(st + a_d0 + 16384, Alo + a_s0 + k0);
        cp16(st + a_d1,         Ahi + a_s1 + k0);
        cp16(st + a_d1 + 16384, Alo + a_s1 + k0);
#pragma unroll
        for (int i = 0; i < 4; i++) {
            const size_t bs = (size_t)(k0 + bk[i]) * N + bn + bg[i] * 8;
            cp16(st + 32768 + b_d[i],         Bhi + bs);
            cp16(st + 32768 + b_d[i] + 32768, Blo + bs);
        }
    };

    float acc[2][8][4];
#pragma unroll
    for (int i = 0; i < 2; i++)
#pragma unroll
        for (int j = 0; j < 8; j++)
#pragma unroll
            for (int t = 0; t < 4; t++) acc[i][j][t] = 0.f;

    issue(0, 0); CP_COMMIT();

    const int a_row0 = wm * 32 + (lane & 15);
    const int b_g0   = wn * 8 + (lane >> 4);

    for (int c = 0; c < nchunk; c++) {
        CP_WAIT0();
        __syncthreads();
        if (c + 1 < nchunk) issue((c + 1) & 1, c + 1);
        CP_COMMIT();

        const uint32_t stA = sb + (c & 1) * G2_STG;
        const uint32_t stB = stA + 32768;

#pragma unroll
        for (int ks = 0; ks < 4; ks++) {
            uint32_t ah[2][4], al[2][4];
#pragma unroll
            for (int mt = 0; mt < 2; mt++) {
                const int row = a_row0 + mt * 16;
                const int cgl = ks * 2 + (lane >> 4);
                const uint32_t a = stA + (uint32_t)(row * 128
                                   + ((cgl ^ (row & 7)) << 4));
                ldsm4(ah[mt], a);
                ldsm4(al[mt], a + 16384);
            }
#pragma unroll
            for (int ng = 0; ng < 4; ng++) {
                const int r = ks * 16 + (lane & 15);
                const int g = b_g0 + ng * 2;
                const uint32_t b = stB + (uint32_t)(r * 512 + ((g ^ (r & 7)) << 4));
                uint32_t th[4], tl[4];
                ldsm4t(th, b);
                ldsm4t(tl, b + 32768);
                uint32_t bh0[2] = {th[0], th[1]}, bh1[2] = {th[2], th[3]};
                uint32_t bl0[2] = {tl[0], tl[1]}, bl1[2] = {tl[2], tl[3]};
#pragma unroll
                for (int mt = 0; mt < 2; mt++) {
                    mma16816(acc[mt][2 * ng],     ah[mt], bh0);
                    mma16816(acc[mt][2 * ng + 1], ah[mt], bh1);
                }
#pragma unroll
                for (int mt = 0; mt < 2; mt++) {
                    mma16816(acc[mt][2 * ng],     ah[mt], bl0);
                    mma16816(acc[mt][2 * ng + 1], ah[mt], bl1);
                }
#pragma unroll
                for (int mt = 0; mt < 2; mt++) {
                    mma16816(acc[mt][2 * ng],     al[mt], bh0);
                    mma16816(acc[mt][2 * ng + 1], al[mt], bh1);
                }
            }
        }
    }

    // ---- stage accumulators to smem fp32 ----
    __syncthreads();
    float* Ss = (float*)smem;
    {
        const int r0 = wm * 32 + (lane >> 2);
        const int c0 = wn * 64 + (lane & 3) * 2;
#pragma unroll
        for (int mt = 0; mt < 2; mt++)
#pragma unroll
            for (int nt = 0; nt < 8; nt++) {
                const int r = r0 + mt * 16;
                const int cc = c0 + nt * 8;
                *(float2*)&Ss[r * G2_ESTR + cc] =
                    make_float2(acc[mt][nt][0], acc[mt][nt][1]);
                *(float2*)&Ss[(r + 8) * G2_ESTR + cc] =
                    make_float2(acc[mt][nt][2], acc[mt][nt][3]);
            }
    }
    __syncthreads();

    // QKV epilogue: bias + RoPE(q,k); Q,K -> bf16 hi/lo; V -> single fp16
    {
        uint32_t* Qh = (uint32_t*)g_Qhi;  uint32_t* Ql = (uint32_t*)g_Qlo;
        uint32_t* Kh = (uint32_t*)g_Khi;  uint32_t* Kl = (uint32_t*)g_Klo;
        uint32_t* Vf = (uint32_t*)g_Vf;
        const int tx = tid & 15, ty = tid >> 4;
        const bool rope = (bn < HID + KV_DIM);
#pragma unroll
        for (int i = 0; i < 4; i++) {
            const int row = ty + 32 * i;
            const int m   = bm + row;
            float2 p[8];
#pragma unroll
            for (int j = 0; j < 8; j++) {
                p[j] = *(const float2*)&Ss[row * G2_ESTR + 2 * tx + 32 * j];
                float2 bb = *(const float2*)&bias[bn + 2 * tx + 32 * j];
                p[j].x += bb.x;
                p[j].y += bb.y;
            }
            if (rope) {
#pragma unroll
                for (int jj = 0; jj < 4; jj++) {
                    const int j = (jj & 1) + (jj >> 1) * 4;  // {0,1,4,5}
                    const int d0 = (2 * tx + 32 * j) & 63;
                    const float c0 = g_cos[m * HALF + d0];
                    const float s0 = g_sin[m * HALF + d0];
                    const float c1 = g_cos[m * HALF + d0 + 1];
                    const float s1 = g_sin[m * HALF + d0 + 1];
                    float x1 = p[j].x, x2 = p[j + 2].x;
                    p[j].x     = x1 * c0 - x2 * s0;
                    p[j + 2].x = x2 * c0 + x1 * s0;
                    x1 = p[j].y; x2 = p[j + 2].y;
                    p[j].y     = x1 * c1 - x2 * s1;
                    p[j + 2].y = x2 * c1 + x1 * s1;
                }
            }
#pragma unroll
            for (int j = 0; j < 8; j++) {
                const int col = bn + 2 * tx + 32 * j;
                if (col < HID) {
                    uint32_t hi, lo;
                    split2(p[j].x, p[j].y, hi, lo);
                    const int idx = (m * HID + col) >> 1;
                    Qh[idx] = hi; Ql[idx] = lo;
                } else if (col < HID + KV_DIM) {
                    uint32_t hi, lo;
                    split2(p[j].x, p[j].y, hi, lo);
                    const int idx = (m * KV_DIM + col - HID) >> 1;
                    Kh[idx] = hi; Kl[idx] = lo;
                } else {
                    const int idx = (m * KV_DIM + col - HID - KV_DIM) >> 1;
                    Vf[idx] = pack2h(p[j].x, p[j].y);
                }
            }
        }
    }
}

// ========================= Proj GEMM (fp16 2-term, BK=64) ==================
// BM=128 BN=256 BK=64, 512 threads, 2 stages of 64KB.
// Stage: Ahi[0,16K) Alo[16K,32K) B[32K,64K). Epilogue scratch 133120 B.
#define G4_STG  65536
#define G4_SMEM 135168
#define G4_ESTR 260

__global__ __launch_bounds__(512, 1)
void hmma_gemm_f16(const __half* __restrict__ Ahi,
                   const __half* __restrict__ Alo,
                   const __half* __restrict__ B,
                   const float* __restrict__ bias, float* __restrict__ C,
                   int N, int K)
{
    extern __shared__ char smem[];
    const uint32_t sb = smem_u32(smem);
    const int tid  = threadIdx.x;
    const int lane = tid & 31;
    const int warp = tid >> 5;
    const int wm   = warp >> 2;
    const int wn   = warp & 3;
    const int bm   = blockIdx.y * 128;
    const int bn   = blockIdx.x * 256;
    const int nchunk = K >> 6;

    const int ap0 = tid * 2, ap1 = tid * 2 + 1;
    const int ar0 = ap0 >> 3, ag0 = ap0 & 7;
    const int ar1 = ap1 >> 3, ag1 = ap1 & 7;
    const uint32_t a_d0 = (uint32_t)(ar0 * 128 + ((ag0 ^ (ar0 & 7)) << 4));
    const uint32_t a_d1 = (uint32_t)(ar1 * 128 + ((ag1 ^ (ar1 & 7)) << 4));
    const size_t a_s0 = (size_t)(bm + ar0) * K + ag0 * 8;
    const size_t a_s1 = (size_t)(bm + ar1) * K + ag1 * 8;

    int bk[4], bg[4];
    uint32_t b_d[4];
#pragma unroll
    for (int i = 0; i < 4; i++) {
        const int q = tid * 4 + i;
        bk[i] = q >> 5; bg[i] = q & 31;
        b_d[i] = (uint32_t)(bk[i] * 512 + ((bg[i] ^ (bk[i] & 7)) << 4));
    }

    auto issue = [&](int s, int c) {
        const uint32_t st = sb + s * G4_STG;
        const int k0 = c << 6;
        cp16(st + a_d0,         Ahi + a_s0 + k0);
        cp16(st + a_d0 + 16384, Alo + a_s0 + k0);
        cp16(st + a_d1,         Ahi + a_s1 + k0);
        cp16(st + a_d1 + 16384, Alo + a_s1 + k0);
#pragma unroll
        for (int i = 0; i < 4; i++) {
            const size_t bs = (size_t)(k0 + bk[i]) * N + bn + bg[i] * 8;
            cp16(st + 32768 + b_d[i], B + bs);
        }
    };

    float acc[2][8][4];
#pragma unroll
    for (int i = 0; i < 2; i++)
#pragma unroll
        for (int j = 0; j < 8; j++)
#pragma unroll
            for (int t = 0; t < 4; t++) acc[i][j][t] = 0.f;

    issue(0, 0); CP_COMMIT();

    const int a_row0 = wm * 32 + (lane & 15);
    const int b_g0   = wn * 8 + (lane >> 4);

    for (int c = 0; c < nchunk; c++) {
        CP_WAIT0();
        __syncthreads();
        if (c + 1 < nchunk) issue((c + 1) & 1, c + 1);
        CP_COMMIT();

        const uint32_t stA = sb + (c & 1) * G4_STG;
        const uint32_t stB = stA + 32768;

#pragma unroll
        for (int ks = 0; ks < 4; ks++) {
            uint32_t ah[2][4], al[2][4];
#pragma unroll
            for (int mt = 0; mt < 2; mt++) {
                const int row = a_row0 + mt * 16;
                const int cgl = ks * 2 + (lane >> 4);
                const uint32_t a = stA + (uint32_t)(row * 128
                                   + ((cgl ^ (row & 7)) << 4));
                ldsm4(ah[mt], a);
                ldsm4(al[mt], a + 16384);
            }
#pragma unroll
            for (int ng = 0; ng < 4; ng++) {
                const int r = ks * 16 + (lane & 15);
                const int g = b_g0 + ng * 2;
                const uint32_t b = stB + (uint32_t)(r * 512 + ((g ^ (r & 7)) << 4));
                uint32_t th[4];
                ldsm4t(th, b);
                uint32_t bh0[2] = {th[0], th[1]}, bh1[2] = {th[2], th[3]};
#pragma unroll
                for (int mt = 0; mt < 2; mt++) {
                    mma16816h(acc[mt][2 * ng],     ah[mt], bh0);
                    mma16816h(acc[mt][2 * ng + 1], ah[mt], bh1);
                }
#pragma unroll
                for (int mt = 0; mt < 2; mt++) {
                    mma16816h(acc[mt][2 * ng],     al[mt], bh0);
                    mma16816h(acc[mt][2 * ng + 1], al[mt], bh1);
                }
            }
        }
    }

    // ---- epilogue: bias, fp32 out ----
    __syncthreads();
    float* Ss = (float*)smem;
    {
        const int r0 = wm * 32 + (lane >> 2);
        const int c0 = wn * 64 + (lane & 3) * 2;
#pragma unroll
        for (int mt = 0; mt < 2; mt++)
#pragma unroll
            for (int nt = 0; nt < 8; nt++) {
                const int r = r0 + mt * 16;
                const int cc = c0 + nt * 8;
                *(float2*)&Ss[r * G4_ESTR + cc] =
                    make_float2(acc[mt][nt][0], acc[mt][nt][1]);
                *(float2*)&Ss[(r + 8) * G4_ESTR + cc] =
                    make_float2(acc[mt][nt][2], acc[mt][nt][3]);
            }
    }
    __syncthreads();

    {
        const int tx = tid & 31, ty = tid >> 5;
#pragma unroll
        for (int i = 0; i < 8; i++) {
            const int row = ty + 16 * i;
            const int m   = bm + row;
            float v[8];
#pragma unroll
            for (int j = 0; j < 8; j++)
                v[j] = Ss[row * G4_ESTR + tx + 32 * j] + bias[bn + tx + 32 * j];
#pragma unroll
            for (int j = 0; j < 8; j++)
                C[(size_t)m * N + bn + tx + 32 * j] = v[j];
        }
    }
}

// ========================= Flash attention (R14) ===========================
#define FL_STG  49152
#define FL_SMEM 98304

__global__ __launch_bounds__(256, 1)
void flash_hmma()
{
    extern __shared__ char smem[];
    const uint32_t sb = smem_u32(smem);
    const int tid  = threadIdx.x;
    const int lane = tid & 31;
    const int warp = tid >> 5;
    const int qt   = 15 - (int)blockIdx.x;
    const int h    = blockIdx.y;
    const int kvh  = h >> 2;
    const int wr   = warp * 16;
    const float scale = 0.08838834764831845f;

    const char* pQh = (const char*)g_Qhi;
    const char* pQl = (const char*)g_Qlo;
    const char* pKh = (const char*)g_Khi;
    const char* pKl = (const char*)g_Klo;
    const char* pVf = (const char*)g_Vf;

    {
        const int r = tid >> 1;
        const int gb = (tid & 1) * 8;
#pragma unroll
        for (int i = 0; i < 8; i++) {
            const int g = gb + i;
            const size_t src = ((size_t)(qt * 128 + r) * HID + h * HD + g * 8) * 2;
            const uint32_t off = (uint32_t)(r * 256 + ((g ^ (r & 7)) << 4));
            cp16(sb + off,         pQh + src);
            cp16(sb + 32768 + off, pQl + src);
        }
    }
    CP_COMMIT();
    CP_WAIT0();
    __syncthreads();

    uint32_t qh[8][4], ql[8][4];
    {
        const int r = wr + (lane & 15);
#pragma unroll
        for (int ks = 0; ks < 8; ks++) {
            const int g = ks * 2 + (lane >> 4);
            const uint32_t off = (uint32_t)(r * 256 + ((g ^ (r & 7)) << 4));
            ldsm4(qh[ks], sb + off);
            ldsm4(ql[ks], sb + 32768 + off);
        }
    }
    __syncthreads();

    const int lr = tid >> 2;
    const int lgb = (tid & 3) * 4;
    auto issue = [&](int kt, int s) {
        const uint32_t base = sb + s * FL_STG;
#pragma unroll
        for (int i = 0; i < 4; i++) {
            const int g = lgb + i;
            const size_t src =
                ((size_t)(kt * 64 + lr) * KV_DIM + kvh * HD + g * 8) * 2;
            const uint32_t off = (uint32_t)(lr * 256 + ((g ^ (lr & 7)) << 4));
            cp16(base + off,         pKh + src);
            cp16(base + 16384 + off, pKl + src);
            cp16(base + 32768 + off, pVf + src);
        }
    };

    const int ktmax = 2 * qt + 1;
    issue(0, 0); CP_COMMIT();
    issue(1, 1); CP_COMMIT();

    float o[16][4];
#pragma unroll
    for (int f = 0; f < 16; f++)
#pragma unroll
        for (int e = 0; e < 4; e++) o[f][e] = 0.f;
    float m0 = -1e30f, m1 = -1e30f, l0 = 0.f, l1 = 0.f;

    const int row0 = qt * 128 + wr + (lane >> 2);

    for (int kt = 0; kt <= ktmax; kt++) {
        CP_WAIT1();
        __syncthreads();
        const uint32_t base = sb + (kt & 1) * FL_STG;

        float s[8][4];
#pragma unroll
        for (int f = 0; f < 8; f++)
#pragma unroll
            for (int e = 0; e < 4; e++) s[f][e] = 0.f;

#pragma unroll
        for (int ks = 0; ks < 8; ks++) {
#pragma unroll
            for (int kgp = 0; kgp < 2; kgp++) {
                uint32_t bh[4][2], bl[4][2];
#pragma unroll
                for (int u = 0; u < 2; u++) {
                    const int kg = 2 * kgp + u;
                    const int n = kg * 16 + (lane & 7) + ((lane >> 4) & 1) * 8;
                    const int g = ks * 2 + ((lane >> 3) & 1);
                    const uint32_t off = base
                        + (uint32_t)(n * 256 + ((g ^ (n & 7)) << 4));
                    uint32_t th[4], tl[4];
                    ldsm4(th, off);
                    ldsm4(tl, off + 16384);
                    bh[2 * u][0] = th[0]; bh[2 * u][1] = th[1];
                    bh[2 * u + 1][0] = th[2]; bh[2 * u + 1][1] = th[3];
                    bl[2 * u][0] = tl[0]; bl[2 * u][1] = tl[1];
                    bl[2 * u + 1][0] = tl[2]; bl[2 * u + 1][1] = tl[3];
                }
#pragma unroll
                for (int u = 0; u < 4; u++)
                    mma16816(s[4 * kgp + u], qh[ks], bh[u]);
#pragma unroll
                for (int u = 0; u < 4; u++)
                    mma16816(s[4 * kgp + u], qh[ks], bl[u]);
#pragma unroll
                for (int u = 0; u < 4; u++)
                    mma16816(s[4 * kgp + u], ql[ks], bh[u]);
            }
        }

        const bool need_mask = (kt >= 2 * qt);
        float vmax0 = -1e30f, vmax1 = -1e30f;
#pragma unroll
        for (int f = 0; f < 8; f++) {
            const int colb = kt * 64 + f * 8 + 2 * (lane & 3);
#pragma unroll
            for (int e = 0; e < 2; e++) {
                float v = s[f][e] * scale;
                if (need_mask && (colb + e > row0)) v = -1e30f;
                s[f][e] = v;
                vmax0 = fmaxf(vmax0, v);
                float w = s[f][2 + e] * scale;
                if (need_mask && (colb + e > row0 + 8)) w = -1e30f;
                s[f][2 + e] = w;
                vmax1 = fmaxf(vmax1, w);
            }
        }
        vmax0 = fmaxf(vmax0, __shfl_xor_sync(0xffffffffu, vmax0, 1));
        vmax0 = fmaxf(vmax0, __shfl_xor_sync(0xffffffffu, vmax0, 2));
        vmax1 = fmaxf(vmax1, __shfl_xor_sync(0xffffffffu, vmax1, 1));
        vmax1 = fmaxf(vmax1, __shfl_xor_sync(0xffffffffu, vmax1, 2));

        const float mn0 = fmaxf(m0, vmax0);
        const float mn1 = fmaxf(m1, vmax1);
        const float al0 = __expf(m0 - mn0);
        const float al1 = __expf(m1 - mn1);
        m0 = mn0; m1 = mn1;

        float sum0 = 0.f, sum1 = 0.f;
#pragma unroll
        for (int f = 0; f < 8; f++) {
            s[f][0] = __expf(s[f][0] - mn0); sum0 += s[f][0];
            s[f][1] = __expf(s[f][1] - mn0); sum0 += s[f][1];
            s[f][2] = __expf(s[f][2] - mn1); sum1 += s[f][2];
            s[f][3] = __expf(s[f][3] - mn1); sum1 += s[f][3];
        }
        sum0 += __shfl_xor_sync(0xffffffffu, sum0, 1);
        sum0 += __shfl_xor_sync(0xffffffffu, sum0, 2);
        sum1 += __shfl_xor_sync(0xffffffffu, sum1, 1);
        sum1 += __shfl_xor_sync(0xffffffffu, sum1, 2);
        l0 = l0 * al0 + sum0;
        l1 = l1 * al1 + sum1;

#pragma unroll
        for (int f = 0; f < 16; f++) {
            o[f][0] *= al0; o[f][1] *= al0;
            o[f][2] *= al1; o[f][3] *= al1;
        }

#pragma unroll
        for (int ks = 0; ks < 4; ks++) {
            uint32_t ph[4], pl[4];
            split2h(s[2 * ks][0],     s[2 * ks][1],     ph[0], pl[0]);
            split2h(s[2 * ks][2],     s[2 * ks][3],     ph[1], pl[1]);
            split2h(s[2 * ks + 1][0], s[2 * ks + 1][1], ph[2], pl[2]);
            split2h(s[2 * ks + 1][2], s[2 * ks + 1][3], ph[3], pl[3]);
            const int r = ks * 16 + (lane & 15);
#pragma unroll
            for (int ngp = 0; ngp < 4; ngp++) {
                uint32_t bv[4][2];
#pragma unroll
                for (int u = 0; u < 2; u++) {
                    const int ng = 2 * ngp + u;
                    const int g = ng * 2 + (lane >> 4);
                    const uint32_t off = base + 32768
                        + (uint32_t)(r * 256 + ((g ^ (r & 7)) << 4));
                    uint32_t tv[4];
                    ldsm4t(tv, off);
                    bv[2 * u][0] = tv[0]; bv[2 * u][1] = tv[1];
                    bv[2 * u + 1][0] = tv[2]; bv[2 * u + 1][1] = tv[3];
                }
#pragma unroll
                for (int u = 0; u < 4; u++)
                    mma16816h(o[4 * ngp + u], ph, bv[u]);
#pragma unroll
                for (int u = 0; u < 4; u++)
                    mma16816h(o[4 * ngp + u], pl, bv[u]);
            }
        }

        __syncthreads();
        if (kt + 2 <= ktmax) issue(kt + 2, kt & 1);
        CP_COMMIT();
    }

    const float inv0 = 1.f / l0;
    const float inv1 = 1.f / l1;
    uint32_t* Ah = (uint32_t*)g_Ahf;
    uint32_t* Al = (uint32_t*)g_Alf;
    const int colb = h * HD + 2 * (lane & 3);
#pragma unroll
    for (int f = 0; f < 16; f++) {
        uint32_t hi, lo;
        const int idx0 = (row0 * HID + colb + f * 8) >> 1;
        split2h(o[f][0] * inv0, o[f][1] * inv0, hi, lo);
        Ah[idx0] = hi; Al[idx0] = lo;
        const int idx1 = ((row0 + 8) * HID + colb + f * 8) >> 1;
        split2h(o[f][2] * inv1, o[f][3] * inv1, hi, lo);
        Ah[idx1] = hi; Al[idx1] = lo;
    }
}

// ========================= launch ===========================================
extern "C" void kernel_launch(void* const* d_in, const int* in_sizes, int n_in,
                              void* d_out, int out_size)
{
    (void)in_sizes; (void)n_in; (void)out_size;
    const int*   positions = (const int*)  d_in[0];
    const float* X         = (const float*)d_in[1];
    const float* Wqkv      = (const float*)d_in[2];
    const float* bqkv      = (const float*)d_in[3];
    const float* Wproj     = (const float*)d_in[4];
    const float* bproj     = (const float*)d_in[5];
    float* out = (float*)d_out;

    __nv_bfloat16 *xhi, *xlo, *wqhi, *wqlo;
    __half *wpf, *ahf, *alf;
    cudaGetSymbolAddress((void**)&xhi,  g_Xhi);
    cudaGetSymbolAddress((void**)&xlo,  g_Xlo);
    cudaGetSymbolAddress((void**)&wqhi, g_Wq_hi);
    cudaGetSymbolAddress((void**)&wqlo, g_Wq_lo);
    cudaGetSymbolAddress((void**)&wpf,  g_Wpf);
    cudaGetSymbolAddress((void**)&ahf,  g_Ahf);
    cudaGetSymbolAddress((void**)&alf,  g_Alf);

    // 1) rope (#1), X split (#2), Wqkv split (#3)
    rope_table_kernel<<<(S_LEN * HALF + 255) / 256, 256>>>(positions);
    {
        int n4 = S_LEN * HID / 4;
        split_kernel<<<(n4 + 255) / 256, 256>>>((const float4*)X,
                                                (uint2*)xhi, (uint2*)xlo, n4);
    }
    {
        int n4 = HID * QKV_N / 4;
        split_kernel<<<(n4 + 255) / 256, 256>>>((const float4*)Wqkv,
                                                (uint2*)wqhi, (uint2*)wqlo, n4);
    }

    // 2) QKV GEMM (#4 — ncu-profiled slot)
    cudaFuncSetAttribute(hmma_gemm2, cudaFuncAttributeMaxDynamicSharedMemorySize,
                         G2_SMEM);
    {
        dim3 grid(QKV_N / 256, S_LEN / 128);
        hmma_gemm2<<<grid, 512, G2_SMEM>>>(xhi, xlo, wqhi, wqlo, bqkv,
                                           QKV_N, HID);
    }

    // 3) Flash attention (#5)
    cudaFuncSetAttribute(flash_hmma, cudaFuncAttributeMaxDynamicSharedMemorySize,
                         FL_SMEM);
    {
        dim3 grid(S_LEN / 128, NH);
        flash_hmma<<<grid, 256, FL_SMEM>>>();
    }

    // 4) Wproj fp16 split (#6), proj GEMM (#7)
    {
        int n4 = HID * HID / 4;
        split_half_kernel<<<(n4 + 255) / 256, 256>>>((const float4*)Wproj,
                                                     (uint2*)wpf, n4);
    }
    cudaFuncSetAttribute(hmma_gemm_f16,
                         cudaFuncAttributeMaxDynamicSharedMemorySize, G4_SMEM);
    {
        dim3 grid(HID / 256, S_LEN / 128);
        hmma_gemm_f16<<<grid, 512, G4_SMEM>>>(ahf, alf, wpf, bproj, out,
                                              HID, HID);
    }
}

// round 16
// speedup vs baseline: 1.2275x; 1.2275x over previous
#include <cuda_runtime.h>
#include <cuda_bf16.h>
#include <cuda_fp16.h>
#include <math.h>
#include <stdint.h>

// ---------------------------------------------------------------------------
// CodeShellAttention round 16:
//   - GEMM mainloops reverted to R14 (BK=32, 4-stage cp.async — best measured).
//   - Flash P*V: 1-term fp16 (P single fp16; linear path, ~1.4e-4 added).
//   - Proj GEMM: 1-term fp16 (attn single fp16 x Wproj single fp16).
//   - QKV GEMM / Q,K paths: bf16 3-term (softmax-amplified) — unchanged.
// ---------------------------------------------------------------------------

#define S_LEN  2048
#define HID    4096
#define NH     32
#define NKV    8
#define HD     128
#define QKV_N  6144
#define KV_DIM 1024
#define HALF   64

__device__ float g_cos[S_LEN * HALF];
__device__ float g_sin[S_LEN * HALF];

__device__ __nv_bfloat16 g_Xhi[S_LEN * HID];
__device__ __nv_bfloat16 g_Xlo[S_LEN * HID];
__device__ __nv_bfloat16 g_Wq_hi[HID * QKV_N];
__device__ __nv_bfloat16 g_Wq_lo[HID * QKV_N];
__device__ __half        g_Wpf[HID * HID];

__device__ __nv_bfloat16 g_Qhi[S_LEN * HID];
__device__ __nv_bfloat16 g_Qlo[S_LEN * HID];
__device__ __nv_bfloat16 g_Khi[S_LEN * KV_DIM];
__device__ __nv_bfloat16 g_Klo[S_LEN * KV_DIM];
__device__ __half        g_Vf[S_LEN * KV_DIM];
__device__ __half        g_Af[S_LEN * HID];     // attn, single fp16

// ========================= helpers =========================================
__device__ __forceinline__ uint32_t smem_u32(const void* p) {
    uint32_t a;
    asm("{ .reg .u64 t; cvta.to.shared.u64 t, %1; cvt.u32.u64 %0, t; }"
        : "=r"(a) : "l"(p));
    return a;
}

__device__ __forceinline__ void ldsm4(uint32_t* r, uint32_t addr) {
    asm volatile("ldmatrix.sync.aligned.m8n8.x4.shared.b16 {%0,%1,%2,%3}, [%4];"
                 : "=r"(r[0]), "=r"(r[1]), "=r"(r[2]), "=r"(r[3]) : "r"(addr));
}

__device__ __forceinline__ void ldsm4t(uint32_t* r, uint32_t addr) {
    asm volatile("ldmatrix.sync.aligned.m8n8.x4.trans.shared.b16 {%0,%1,%2,%3}, [%4];"
                 : "=r"(r[0]), "=r"(r[1]), "=r"(r[2]), "=r"(r[3]) : "r"(addr));
}

__device__ __forceinline__ void mma16816(float* d, const uint32_t* a,
                                         const uint32_t* b) {
    asm volatile(
        "mma.sync.aligned.m16n8k16.row.col.f32.bf16.bf16.f32 "
        "{%0,%1,%2,%3}, {%4,%5,%6,%7}, {%8,%9}, {%0,%1,%2,%3};"
        : "+f"(d[0]), "+f"(d[1]), "+f"(d[2]), "+f"(d[3])
        : "r"(a[0]), "r"(a[1]), "r"(a[2]), "r"(a[3]), "r"(b[0]), "r"(b[1]));
}

__device__ __forceinline__ void mma16816h(float* d, const uint32_t* a,
                                          const uint32_t* b) {
    asm volatile(
        "mma.sync.aligned.m16n8k16.row.col.f32.f16.f16.f32 "
        "{%0,%1,%2,%3}, {%4,%5,%6,%7}, {%8,%9}, {%0,%1,%2,%3};"
        : "+f"(d[0]), "+f"(d[1]), "+f"(d[2]), "+f"(d[3])
        : "r"(a[0]), "r"(a[1]), "r"(a[2]), "r"(a[3]), "r"(b[0]), "r"(b[1]));
}

__device__ __forceinline__ void split2(float x, float y, uint32_t& hi, uint32_t& lo)
{
    uint32_t bx = __float_as_uint(x), by = __float_as_uint(y);
    hi = __byte_perm(bx, by, 0x7632);
    float hx = __uint_as_float(bx & 0xFFFF0000u);
    float hy = __uint_as_float(by & 0xFFFF0000u);
    __nv_bfloat162 l = __floats2bfloat162_rn(x - hx, y - hy);
    lo = *reinterpret_cast<uint32_t*>(&l);
}

__device__ __forceinline__ uint32_t pack2h(float x, float y)
{
    __half2 h = __floats2half2_rn(x, y);
    return *reinterpret_cast<uint32_t*>(&h);
}

__device__ __forceinline__ void cp16(uint32_t saddr, const void* gaddr) {
    asm volatile("cp.async.cg.shared.global [%0], [%1], 16;"
                 :: "r"(saddr), "l"(gaddr) : "memory");
}
#define CP_COMMIT() asm volatile("cp.async.commit_group;" ::: "memory")
#define CP_WAIT0()  asm volatile("cp.async.wait_group 0;" ::: "memory")
#define CP_WAIT1()  asm volatile("cp.async.wait_group 1;" ::: "memory")
#define CP_WAIT2()  asm volatile("cp.async.wait_group 2;" ::: "memory")

// ========================= RoPE tables =====================================
__global__ void rope_table_kernel(const int* __restrict__ positions)
{
    int i = blockIdx.x * blockDim.x + threadIdx.x;
    if (i >= S_LEN * HALF) return;
    int m = i >> 6;
    int d = i & 63;
    double p    = (double)positions[m];
    double invf = pow(10000.0, -((double)d) / 64.0);
    double a    = p * invf;
    g_cos[i] = (float)cos(a);
    g_sin[i] = (float)sin(a);
}

// ========================= split passes ====================================
__global__ void split_kernel(const float4* __restrict__ in,
                             uint2* __restrict__ hi, uint2* __restrict__ lo,
                             int n4)
{
    int i = blockIdx.x * blockDim.x + threadIdx.x;
    if (i >= n4) return;
    float4 v = in[i];
    uint32_t h01, l01, h23, l23;
    split2(v.x, v.y, h01, l01);
    split2(v.z, v.w, h23, l23);
    hi[i] = make_uint2(h01, h23);
    lo[i] = make_uint2(l01, l23);
}

__global__ void split_half_kernel(const float4* __restrict__ in,
                                  uint2* __restrict__ out, int n4)
{
    int i = blockIdx.x * blockDim.x + threadIdx.x;
    if (i >= n4) return;
    float4 v = in[i];
    out[i] = make_uint2(pack2h(v.x, v.y), pack2h(v.z, v.w));
}

// ========================= QKV GEMM (bf16 3-term, R14) =====================
// BM=128 BN=256 BK=32, 512 threads, 4 stages of 48KB.
#define G2_STG_A 8192
#define G2_STG_B 16384
#define G2_STG   49152
#define G2_SMEM  (4 * G2_STG)
#define G2_ESTR  260

__global__ __launch_bounds__(512, 1)
void hmma_gemm2(const __nv_bfloat16* __restrict__ Ahi,
                const __nv_bfloat16* __restrict__ Alo,
                const __nv_bfloat16* __restrict__ Bhi,
                const __nv_bfloat16* __restrict__ Blo,
                const float* __restrict__ bias,
                int N, int K)
{
    extern __shared__ char smem[];
    const uint32_t sb = smem_u32(smem);
    const int tid  = threadIdx.x;
    const int lane = tid & 31;
    const int warp = tid >> 5;
    const int wm   = warp >> 2;
    const int wn   = warp & 3;
    const int bm   = blockIdx.y * 128;
    const int bn   = blockIdx.x * 256;
    const int nchunk = K >> 5;

    const int am = tid >> 2, acg = tid & 3;
    const uint32_t a_dst = (uint32_t)(am * 64 + ((acg ^ ((am >> 1) & 3)) << 4));
    const size_t a_src0 = (size_t)(bm + am) * K + acg * 8;

    const int bk0 = (tid * 2) >> 5, bg0 = (tid * 2) & 31;
    const int bk1 = (tid * 2 + 1) >> 5, bg1 = (tid * 2 + 1) & 31;
    const uint32_t b_dst0 = (uint32_t)(bk0 * 512 + ((bg0 ^ (bk0 & 7)) << 4));
    const uint32_t b_dst1 = (uint32_t)(bk1 * 512 + ((bg1 ^ (bk1 & 7)) << 4));

    auto issue = [&](int s, int c) {
        const uint32_t st = sb + s * G2_STG;
        const int k0 = c << 5;
        cp16(st + a_dst,            Ahi + a_src0 + k0);
        cp16(st + a_dst + G2_STG_A, Alo + a_src0 + k0);
        const size_t bs0 = (size_t)(k0 + bk0) * N + bn + bg0 * 8;
        const size_t bs1 = (size_t)(k0 + bk1) * N + bn + bg1 * 8;
        cp16(st + 16384 + b_dst0,            Bhi + bs0);
        cp16(st + 16384 + b_dst0 + G2_STG_B, Blo + bs0);
        cp16(st + 16384 + b_dst1,            Bhi + bs1);
        cp16(st + 16384 + b_dst1 + G2_STG_B, Blo + bs1);
    };

    float acc[2][8][4];
#pragma unroll
    for (int i = 0; i < 2; i++)
#pragma unroll
        for (int j = 0; j < 8; j++)
#pragma unroll
            for (int t = 0; t < 4; t++) acc[i][j][t] = 0.f;

    issue(0, 0); CP_COMMIT();
    issue(1, 1); CP_COMMIT();
    issue(2, 2); CP_COMMIT();

    const int a_row0 = wm * 32 + (lane & 15);
    const int b_g0   = wn * 8 + (lane >> 4);

    for (int c = 0; c < nchunk; c++) {
        CP_WAIT2();
        __syncthreads();
        if (c + 3 < nchunk) issue((c + 3) & 3, c + 3);
        CP_COMMIT();

        const uint32_t stA = sb + (c & 3) * G2_STG;
        const uint32_t stB = stA + 16384;

#pragma unroll
        for (int ks = 0; ks < 2; ks++) {
            uint32_t ah[2][4], al[2][4];
#pragma unroll
            for (int mt = 0; mt < 2; mt++) {
                const int row = a_row0 + mt * 16;
                const int cgl = ks * 2 + (lane >> 4);
                const uint32_t a = stA + (uint32_t)(row * 64
                                   + ((cgl ^ ((row >> 1) & 3)) << 4));
                ldsm4(ah[mt], a);
                ldsm4(al[mt], a + G2_STG_A);
            }
#pragma unroll
            for (int ng = 0; ng < 4; ng++) {
                const int r = ks * 16 + (lane & 15);
                const int g = b_g0 + ng * 2;
                const uint32_t b = stB + (uint32_t)(r * 512 + ((g ^ (r & 7)) << 4));
                uint32_t th[4], tl[4];
                ldsm4t(th, b);
                ldsm4t(tl, b + G2_STG_B);
                uint32_t bh0[2] = {th[0], th[1]}, bh1[2] = {th[2], th[3]};
                uint32_t bl0[2] = {tl[0], tl[1]}, bl1[2] = {tl[2], tl[3]};
#pragma unroll
                for (int mt = 0; mt < 2; mt++) {
                    mma16816(acc[mt][2 * ng],     ah[mt], bh0);
                    mma16816(acc[mt][2 * ng + 1], ah[mt], bh1);
                }
#pragma unroll
                for (int mt = 0; mt < 2; mt++) {
                    mma16816(acc[mt][2 * ng],     ah[mt], bl0);
                    mma16816(acc[mt][2 * ng + 1], ah[mt], bl1);
                }
#pragma unroll
                for (int mt = 0; mt < 2; mt++) {
                    mma16816(acc[mt][2 * ng],     al[mt], bh0);
                    mma16816(acc[mt][2 * ng + 1], al[mt], bh1);
                }
            }
        }
    }

    // ---- stage accumulators to smem fp32 ----
    __syncthreads();
    float* Ss = (float*)smem;
    {
        const int r0 = wm * 32 + (lane >> 2);
        const int c0 = wn * 64 + (lane & 3) * 2;
#pragma unroll
        for (int mt = 0; mt < 2; mt++)
#pragma unroll
            for (int nt = 0; nt < 8; nt++) {
                const int r = r0 + mt * 16;
                const int cc = c0 + nt * 8;
                *(float2*)&Ss[r * G2_ESTR + cc] =
                    make_float2(acc[mt][nt][0], acc[mt][nt][1]);
                *(float2*)&Ss[(r + 8) * G2_ESTR + cc] =
                    make_float2(acc[mt][nt][2], acc[mt][nt][3]);
            }
    }
    __syncthreads();

    // QKV epilogue: bias + RoPE(q,k); Q,K -> bf16 hi/lo; V -> single fp16
    {
        uint32_t* Qh = (uint32_t*)g_Qhi;  uint32_t* Ql = (uint32_t*)g_Qlo;
        uint32_t* Kh = (uint32_t*)g_Khi;  uint32_t* Kl = (uint32_t*)g_Klo;
        uint32_t* Vf = (uint32_t*)g_Vf;
        const int tx = tid & 15, ty = tid >> 4;
        const bool rope = (bn < HID + KV_DIM);
#pragma unroll
        for (int i = 0; i < 4; i++) {
            const int row = ty + 32 * i;
            const int m   = bm + row;
            float2 p[8];
#pragma unroll
            for (int j = 0; j < 8; j++) {
                p[j] = *(const float2*)&Ss[row * G2_ESTR + 2 * tx + 32 * j];
                float2 bb = *(const float2*)&bias[bn + 2 * tx + 32 * j];
                p[j].x += bb.x;
                p[j].y += bb.y;
            }
            if (rope) {
#pragma unroll
                for (int jj = 0; jj < 4; jj++) {
                    const int j = (jj & 1) + (jj >> 1) * 4;  // {0,1,4,5}
                    const int d0 = (2 * tx + 32 * j) & 63;
                    const float c0 = g_cos[m * HALF + d0];
                    const float s0 = g_sin[m * HALF + d0];
                    const float c1 = g_cos[m * HALF + d0 + 1];
                    const float s1 = g_sin[m * HALF + d0 + 1];
                    float x1 = p[j].x, x2 = p[j + 2].x;
                    p[j].x     = x1 * c0 - x2 * s0;
                    p[j + 2].x = x2 * c0 + x1 * s0;
                    x1 = p[j].y; x2 = p[j + 2].y;
                    p[j].y     = x1 * c1 - x2 * s1;
                    p[j + 2].y = x2 * c1 + x1 * s1;
                }
            }
#pragma unroll
            for (int j = 0; j < 8; j++) {
                const int col = bn + 2 * tx + 32 * j;
                if (col < HID) {
                    uint32_t hi, lo;
                    split2(p[j].x, p[j].y, hi, lo);
                    const int idx = (m * HID + col) >> 1;
                    Qh[idx] = hi; Ql[idx] = lo;
                } else if (col < HID + KV_DIM) {
                    uint32_t hi, lo;
                    split2(p[j].x, p[j].y, hi, lo);
                    const int idx = (m * KV_DIM + col - HID) >> 1;
                    Kh[idx] = hi; Kl[idx] = lo;
                } else {
                    const int idx = (m * KV_DIM + col - HID - KV_DIM) >> 1;
                    Vf[idx] = pack2h(p[j].x, p[j].y);
                }
            }
        }
    }
}

// ========================= Proj GEMM (fp16 1-term) =========================
// BM=128 BN=256 BK=32, 512 threads, 4 stages of 24KB.
// Stage: A[0,8K) B[8K,24K). Epilogue scratch 133120 B -> SMEM 135168.
#define G4_STG  24576
#define G4_SMEM 135168
#define G4_ESTR 260

__global__ __launch_bounds__(512, 1)
void hmma_gemm_f16(const __half* __restrict__ A,
                   const __half* __restrict__ B,
                   const float* __restrict__ bias, float* __restrict__ C,
                   int N, int K)
{
    extern __shared__ char smem[];
    const uint32_t sb = smem_u32(smem);
    const int tid  = threadIdx.x;
    const int lane = tid & 31;
    const int warp = tid >> 5;
    const int wm   = warp >> 2;
    const int wn   = warp & 3;
    const int bm   = blockIdx.y * 128;
    const int bn   = blockIdx.x * 256;
    const int nchunk = K >> 5;

    const int am = tid >> 2, acg = tid & 3;
    const uint32_t a_dst = (uint32_t)(am * 64 + ((acg ^ ((am >> 1) & 3)) << 4));
    const size_t a_src0 = (size_t)(bm + am) * K + acg * 8;

    const int bk0 = (tid * 2) >> 5, bg0 = (tid * 2) & 31;
    const int bk1 = (tid * 2 + 1) >> 5, bg1 = (tid * 2 + 1) & 31;
    const uint32_t b_dst0 = (uint32_t)(bk0 * 512 + ((bg0 ^ (bk0 & 7)) << 4));
    const uint32_t b_dst1 = (uint32_t)(bk1 * 512 + ((bg1 ^ (bk1 & 7)) << 4));

    auto issue = [&](int s, int c) {
        const uint32_t st = sb + s * G4_STG;
        const int k0 = c << 5;
        cp16(st + a_dst, A + a_src0 + k0);
        const size_t bs0 = (size_t)(k0 + bk0) * N + bn + bg0 * 8;
        const size_t bs1 = (size_t)(k0 + bk1) * N + bn + bg1 * 8;
        cp16(st + 8192 + b_dst0, B + bs0);
        cp16(st + 8192 + b_dst1, B + bs1);
    };

    float acc[2][8][4];
#pragma unroll
    for (int i = 0; i < 2; i++)
#pragma unroll
        for (int j = 0; j < 8; j++)
#pragma unroll
            for (int t = 0; t < 4; t++) acc[i][j][t] = 0.f;

    issue(0, 0); CP_COMMIT();
    issue(1, 1); CP_COMMIT();
    issue(2, 2); CP_COMMIT();

    const int a_row0 = wm * 32 + (lane & 15);
    const int b_g0   = wn * 8 + (lane >> 4);

    for (int c = 0; c < nchunk; c++) {
        CP_WAIT2();
        __syncthreads();
        if (c + 3 < nchunk) issue((c + 3) & 3, c + 3);
        CP_COMMIT();

        const uint32_t stA = sb + (c & 3) * G4_STG;
        const uint32_t stB = stA + 8192;

#pragma unroll
        for (int ks = 0; ks < 2; ks++) {
            uint32_t ah[2][4];
#pragma unroll
            for (int mt = 0; mt < 2; mt++) {
                const int row = a_row0 + mt * 16;
                const int cgl = ks * 2 + (lane >> 4);
                const uint32_t a = stA + (uint32_t)(row * 64
                                   + ((cgl ^ ((row >> 1) & 3)) << 4));
                ldsm4(ah[mt], a);
            }
#pragma unroll
            for (int ng = 0; ng < 4; ng++) {
                const int r = ks * 16 + (lane & 15);
                const int g = b_g0 + ng * 2;
                const uint32_t b = stB + (uint32_t)(r * 512 + ((g ^ (r & 7)) << 4));
                uint32_t th[4];
                ldsm4t(th, b);
                uint32_t bh0[2] = {th[0], th[1]}, bh1[2] = {th[2], th[3]};
#pragma unroll
                for (int mt = 0; mt < 2; mt++) {
                    mma16816h(acc[mt][2 * ng],     ah[mt], bh0);
                    mma16816h(acc[mt][2 * ng + 1], ah[mt], bh1);
                }
            }
        }
    }

    // ---- epilogue: bias, fp32 out ----
    __syncthreads();
    float* Ss = (float*)smem;
    {
        const int r0 = wm * 32 + (lane >> 2);
        const int c0 = wn * 64 + (lane & 3) * 2;
#pragma unroll
        for (int mt = 0; mt < 2; mt++)
#pragma unroll
            for (int nt = 0; nt < 8; nt++) {
                const int r = r0 + mt * 16;
                const int cc = c0 + nt * 8;
                *(float2*)&Ss[r * G4_ESTR + cc] =
                    make_float2(acc[mt][nt][0], acc[mt][nt][1]);
                *(float2*)&Ss[(r + 8) * G4_ESTR + cc] =
                    make_float2(acc[mt][nt][2], acc[mt][nt][3]);
            }
    }
    __syncthreads();

    {
        const int tx = tid & 31, ty = tid >> 5;
#pragma unroll
        for (int i = 0; i < 8; i++) {
            const int row = ty + 16 * i;
            const int m   = bm + row;
            float v[8];
#pragma unroll
            for (int j = 0; j < 8; j++)
                v[j] = Ss[row * G4_ESTR + tx + 32 * j] + bias[bn + tx + 32 * j];
#pragma unroll
            for (int j = 0; j < 8; j++)
                C[(size_t)m * N + bn + tx + 32 * j] = v[j];
        }
    }
}

// ========================= Flash attention =================================
// QK^T bf16 3-term; P*V fp16 1-term (P single fp16, V single fp16).
// Smem: 2 stages x 48KB: Khi[0,16K) Klo[16K,32K) Vf[32K,48K).
#define FL_STG  49152
#define FL_SMEM 98304

__global__ __launch_bounds__(256, 1)
void flash_hmma()
{
    extern __shared__ char smem[];
    const uint32_t sb = smem_u32(smem);
    const int tid  = threadIdx.x;
    const int lane = tid & 31;
    const int warp = tid >> 5;
    const int qt   = 15 - (int)blockIdx.x;
    const int h    = blockIdx.y;
    const int kvh  = h >> 2;
    const int wr   = warp * 16;
    const float scale = 0.08838834764831845f;

    const char* pQh = (const char*)g_Qhi;
    const char* pQl = (const char*)g_Qlo;
    const char* pKh = (const char*)g_Khi;
    const char* pKl = (const char*)g_Klo;
    const char* pVf = (const char*)g_Vf;

    {
        const int r = tid >> 1;
        const int gb = (tid & 1) * 8;
#pragma unroll
        for (int i = 0; i < 8; i++) {
            const int g = gb + i;
            const size_t src = ((size_t)(qt * 128 + r) * HID + h * HD + g * 8) * 2;
            const uint32_t off = (uint32_t)(r * 256 + ((g ^ (r & 7)) << 4));
            cp16(sb + off,         pQh + src);
            cp16(sb + 32768 + off, pQl + src);
        }
    }
    CP_COMMIT();
    CP_WAIT0();
    __syncthreads();

    uint32_t qh[8][4], ql[8][4];
    {
        const int r = wr + (lane & 15);
#pragma unroll
        for (int ks = 0; ks < 8; ks++) {
            const int g = ks * 2 + (lane >> 4);
            const uint32_t off = (uint32_t)(r * 256 + ((g ^ (r & 7)) << 4));
            ldsm4(qh[ks], sb + off);
            ldsm4(ql[ks], sb + 32768 + off);
        }
    }
    __syncthreads();

    const int lr = tid >> 2;
    const int lgb = (tid & 3) * 4;
    auto issue = [&](int kt, int s) {
        const uint32_t base = sb + s * FL_STG;
#pragma unroll
        for (int i = 0; i < 4; i++) {
            const int g = lgb + i;
            const size_t src =
                ((size_t)(kt * 64 + lr) * KV_DIM + kvh * HD + g * 8) * 2;
            const uint32_t off = (uint32_t)(lr * 256 + ((g ^ (lr & 7)) << 4));
            cp16(base + off,         pKh + src);
            cp16(base + 16384 + off, pKl + src);
            cp16(base + 32768 + off, pVf + src);
        }
    };

    const int ktmax = 2 * qt + 1;
    issue(0, 0); CP_COMMIT();
    issue(1, 1); CP_COMMIT();

    float o[16][4];
#pragma unroll
    for (int f = 0; f < 16; f++)
#pragma unroll
        for (int e = 0; e < 4; e++) o[f][e] = 0.f;
    float m0 = -1e30f, m1 = -1e30f, l0 = 0.f, l1 = 0.f;

    const int row0 = qt * 128 + wr + (lane >> 2);

    for (int kt = 0; kt <= ktmax; kt++) {
        CP_WAIT1();
        __syncthreads();
        const uint32_t base = sb + (kt & 1) * FL_STG;

        float s[8][4];
#pragma unroll
        for (int f = 0; f < 8; f++)
#pragma unroll
            for (int e = 0; e < 4; e++) s[f][e] = 0.f;

        // S = Q K^T (bf16 3-term)
#pragma unroll
        for (int ks = 0; ks < 8; ks++) {
#pragma unroll
            for (int kgp = 0; kgp < 2; kgp++) {
                uint32_t bh[4][2], bl[4][2];
#pragma unroll
                for (int u = 0; u < 2; u++) {
                    const int kg = 2 * kgp + u;
                    const int n = kg * 16 + (lane & 7) + ((lane >> 4) & 1) * 8;
                    const int g = ks * 2 + ((lane >> 3) & 1);
                    const uint32_t off = base
                        + (uint32_t)(n * 256 + ((g ^ (n & 7)) << 4));
                    uint32_t th[4], tl[4];
                    ldsm4(th, off);
                    ldsm4(tl, off + 16384);
                    bh[2 * u][0] = th[0]; bh[2 * u][1] = th[1];
                    bh[2 * u + 1][0] = th[2]; bh[2 * u + 1][1] = th[3];
                    bl[2 * u][0] = tl[0]; bl[2 * u][1] = tl[1];
                    bl[2 * u + 1][0] = tl[2]; bl[2 * u + 1][1] = tl[3];
                }
#pragma unroll
                for (int u = 0; u < 4; u++)
                    mma16816(s[4 * kgp + u], qh[ks], bh[u]);
#pragma unroll
                for (int u = 0; u < 4; u++)
                    mma16816(s[4 * kgp + u], qh[ks], bl[u]);
#pragma unroll
                for (int u = 0; u < 4; u++)
                    mma16816(s[4 * kgp + u], ql[ks], bh[u]);
            }
        }

        const bool need_mask = (kt >= 2 * qt);
        float vmax0 = -1e30f, vmax1 = -1e30f;
#pragma unroll
        for (int f = 0; f < 8; f++) {
            const int colb = kt * 64 + f * 8 + 2 * (lane & 3);
#pragma unroll
            for (int e = 0; e < 2; e++) {
                float v = s[f][e] * scale;
                if (need_mask && (colb + e > row0)) v = -1e30f;
                s[f][e] = v;
                vmax0 = fmaxf(vmax0, v);
                float w = s[f][2 + e] * scale;
                if (need_mask && (colb + e > row0 + 8)) w = -1e30f;
                s[f][2 + e] = w;
                vmax1 = fmaxf(vmax1, w);
            }
        }
        vmax0 = fmaxf(vmax0, __shfl_xor_sync(0xffffffffu, vmax0, 1));
        vmax0 = fmaxf(vmax0, __shfl_xor_sync(0xffffffffu, vmax0, 2));
        vmax1 = fmaxf(vmax1, __shfl_xor_sync(0xffffffffu, vmax1, 1));
        vmax1 = fmaxf(vmax1, __shfl_xor_sync(0xffffffffu, vmax1, 2));

        const float mn0 = fmaxf(m0, vmax0);
        const float mn1 = fmaxf(m1, vmax1);
        const float al0 = __expf(m0 - mn0);
        const float al1 = __expf(m1 - mn1);
        m0 = mn0; m1 = mn1;

        float sum0 = 0.f, sum1 = 0.f;
#pragma unroll
        for (int f = 0; f < 8; f++) {
            s[f][0] = __expf(s[f][0] - mn0); sum0 += s[f][0];
            s[f][1] = __expf(s[f][1] - mn0); sum0 += s[f][1];
            s[f][2] = __expf(s[f][2] - mn1); sum1 += s[f][2];
            s[f][3] = __expf(s[f][3] - mn1); sum1 += s[f][3];
        }
        sum0 += __shfl_xor_sync(0xffffffffu, sum0, 1);
        sum0 += __shfl_xor_sync(0xffffffffu, sum0, 2);
        sum1 += __shfl_xor_sync(0xffffffffu, sum1, 1);
        sum1 += __shfl_xor_sync(0xffffffffu, sum1, 2);
        l0 = l0 * al0 + sum0;
        l1 = l1 * al1 + sum1;

#pragma unroll
        for (int f = 0; f < 16; f++) {
            o[f][0] *= al0; o[f][1] *= al0;
            o[f][2] *= al1; o[f][3] *= al1;
        }

        // O += P V  (fp16 1-term: P single fp16, V single fp16)
#pragma unroll
        for (int ks = 0; ks < 4; ks++) {
            uint32_t ph[4];
            ph[0] = pack2h(s[2 * ks][0],     s[2 * ks][1]);
            ph[1] = pack2h(s[2 * ks][2],     s[2 * ks][3]);
            ph[2] = pack2h(s[2 * ks + 1][0], s[2 * ks + 1][1]);
            ph[3] = pack2h(s[2 * ks + 1][2], s[2 * ks + 1][3]);
            const int r = ks * 16 + (lane & 15);
#pragma unroll
            for (int ngp = 0; ngp < 4; ngp++) {
                uint32_t bv[4][2];
#pragma unroll
                for (int u = 0; u < 2; u++) {
                    const int ng = 2 * ngp + u;
                    const int g = ng * 2 + (lane >> 4);
                    const uint32_t off = base + 32768
                        + (uint32_t)(r * 256 + ((g ^ (r & 7)) << 4));
                    uint32_t tv[4];
                    ldsm4t(tv, off);
                    bv[2 * u][0] = tv[0]; bv[2 * u][1] = tv[1];
                    bv[2 * u + 1][0] = tv[2]; bv[2 * u + 1][1] = tv[3];
                }
#pragma unroll
                for (int u = 0; u < 4; u++)
                    mma16816h(o[4 * ngp + u], ph, bv[u]);
            }
        }

        __syncthreads();
        if (kt + 2 <= ktmax) issue(kt + 2, kt & 1);
        CP_COMMIT();
    }

    // finalize: write attn as single fp16 for the proj GEMM
    const float inv0 = 1.f / l0;
    const float inv1 = 1.f / l1;
    uint32_t* Af = (uint32_t*)g_Af;
    const int colb = h * HD + 2 * (lane & 3);
#pragma unroll
    for (int f = 0; f < 16; f++) {
        const int idx0 = (row0 * HID + colb + f * 8) >> 1;
        Af[idx0] = pack2h(o[f][0] * inv0, o[f][1] * inv0);
        const int idx1 = ((row0 + 8) * HID + colb + f * 8) >> 1;
        Af[idx1] = pack2h(o[f][2] * inv1, o[f][3] * inv1);
    }
}

// ========================= launch ===========================================
extern "C" void kernel_launch(void* const* d_in, const int* in_sizes, int n_in,
                              void* d_out, int out_size)
{
    (void)in_sizes; (void)n_in; (void)out_size;
    const int*   positions = (const int*)  d_in[0];
    const float* X         = (const float*)d_in[1];
    const float* Wqkv      = (const float*)d_in[2];
    const float* bqkv      = (const float*)d_in[3];
    const float* Wproj     = (const float*)d_in[4];
    const float* bproj     = (const float*)d_in[5];
    float* out = (float*)d_out;

    __nv_bfloat16 *xhi, *xlo, *wqhi, *wqlo;
    __half *wpf, *af;
    cudaGetSymbolAddress((void**)&xhi,  g_Xhi);
    cudaGetSymbolAddress((void**)&xlo,  g_Xlo);
    cudaGetSymbolAddress((void**)&wqhi, g_Wq_hi);
    cudaGetSymbolAddress((void**)&wqlo, g_Wq_lo);
    cudaGetSymbolAddress((void**)&wpf,  g_Wpf);
    cudaGetSymbolAddress((void**)&af,   g_Af);

    // 1) rope (#1), X split (#2), Wqkv split (#3)
    rope_table_kernel<<<(S_LEN * HALF + 255) / 256, 256>>>(positions);
    {
        int n4 = S_LEN * HID / 4;
        split_kernel<<<(n4 + 255) / 256, 256>>>((const float4*)X,
                                                (uint2*)xhi, (uint2*)xlo, n4);
    }
    {
        int n4 = HID * QKV_N / 4;
        split_kernel<<<(n4 + 255) / 256, 256>>>((const float4*)Wqkv,
                                                (uint2*)wqhi, (uint2*)wqlo, n4);
    }

    // 2) QKV GEMM (#4 — ncu-profiled slot)
    cudaFuncSetAttribute(hmma_gemm2, cudaFuncAttributeMaxDynamicSharedMemorySize,
                         G2_SMEM);
    {
        dim3 grid(QKV_N / 256, S_LEN / 128);
        hmma_gemm2<<<grid, 512, G2_SMEM>>>(xhi, xlo, wqhi, wqlo, bqkv,
                                           QKV_N, HID);
    }

    // 3) Flash attention (#5)
    cudaFuncSetAttribute(flash_hmma, cudaFuncAttributeMaxDynamicSharedMemorySize,
                         FL_SMEM);
    {
        dim3 grid(S_LEN / 128, NH);
        flash_hmma<<<grid, 256, FL_SMEM>>>();
    }

    // 4) Wproj fp16 split (#6), proj GEMM (#7)
    {
        int n4 = HID * HID / 4;
        split_half_kernel<<<(n4 + 255) / 256, 256>>>((const float4*)Wproj,
                                                     (uint2*)wpf, n4);
    }
    cudaFuncSetAttribute(hmma_gemm_f16,
                         cudaFuncAttributeMaxDynamicSharedMemorySize, G4_SMEM);
    {
        dim3 grid(HID / 256, S_LEN / 128);
        hmma_gemm_f16<<<grid, 512, G4_SMEM>>>(af, wpf, bproj, out, HID, HID);
    }
}